// round 10
// baseline (speedup 1.0000x reference)
#include <cuda_runtime.h>
#include <cstdint>

// Shapes are fixed by the problem: B=4, N=M=8192, D=3.
#define NB 4
#define ND 8192
#define TOTAL (2 * NB * ND)   // 65536 (dir, batch, point) slots

// Scratch (device globals — no allocation allowed).
__device__ unsigned g_keys[TOTAL];  // (distbits & 0xFFFFE000) | idx(13b)
__device__ unsigned g_cnt[TOTAL];   // nn target counts per direction

// ---------------- packed f32x2 helpers ----------------
__device__ __forceinline__ unsigned long long pack2(float lo, float hi) {
    unsigned long long r;
    asm("mov.b64 %0, {%1, %2};" : "=l"(r) : "r"(__float_as_uint(lo)), "r"(__float_as_uint(hi)));
    return r;
}
__device__ __forceinline__ unsigned long long fma2(unsigned long long a,
                                                   unsigned long long b,
                                                   unsigned long long c) {
    unsigned long long d;
    asm("fma.rn.f32x2 %0, %1, %2, %3;" : "=l"(d) : "l"(a), "l"(b), "l"(c));
    return d;
}
__device__ __forceinline__ unsigned long long add2(unsigned long long a,
                                                   unsigned long long b) {
    unsigned long long d;
    asm("add.rn.f32x2 %0, %1, %2;" : "=l"(d) : "l"(a), "l"(b));
    return d;
}

// ---------------- init: clear scratch + output ----------------
__global__ void init_k(float* out) {
    int i = blockIdx.x * blockDim.x + threadIdx.x;
    if (i < TOTAL) {
        g_keys[i] = 0xFFFFFFFFu;
        g_cnt[i]  = 0u;
    }
    if (i == 0) out[0] = 0.0f;
}

// ---------------- brute-force NN (both directions fused) ----------------
// grid = 2(dir) * 4(batch) * 32(src chunks of 256) * 4(M splits of 2048) = 1024 blocks
// block = 256 threads, one src point per thread; scans 2048 opposite points
// in 4 shared tiles of 512 points. Tile layout per entry e (2 points a,c):
//   tileF[2e]   = (-2a0, -2c0, -2a1, -2c1)
//   tileF[2e+1] = (-2a2, -2c2,  aa ,  cc )
// read back as ulonglong2 pairs -> direct f32x2 operands, no repacking movs.
__global__ __launch_bounds__(256, 1)
void nn_k(const float* __restrict__ xg, const float* __restrict__ yg) {
    __shared__ float4 tileF[512];
    const ulonglong2* tp = reinterpret_cast<const ulonglong2*>(tileF);

    unsigned bid   = blockIdx.x;
    unsigned split = bid & 3u;  bid >>= 2;
    unsigned chunk = bid & 31u; bid >>= 5;
    unsigned b     = bid & 3u;  bid >>= 2;
    unsigned dir   = bid;       // 0: x->y, 1: y->x

    const float* src = dir ? yg : xg;
    const float* tgt = dir ? xg : yg;

    unsigned p = chunk * 256u + threadIdx.x;
    const float* sp = src + ((size_t)b * ND + p) * 3u;
    float sx0 = sp[0], sx1 = sp[1], sx2 = sp[2];
    float xx  = sx0 * sx0 + sx1 * sx1 + sx2 * sx2;
    unsigned long long x0p = pack2(sx0, sx0);
    unsigned long long x1p = pack2(sx1, sx1);
    unsigned long long x2p = pack2(sx2, sx2);
    unsigned long long xxp = pack2(xx, xx);

    unsigned mask = 0xFFFFE000u;        // keep sign+exp+10 mantissa bits
    asm("" : "+r"(mask));               // force into a register -> single LOP3

    unsigned best = 0xFFFFFFFFu;

    #pragma unroll 1
    for (int t = 0; t < 4; ++t) {
        unsigned jbase = split * 2048u + (unsigned)t * 512u;
        {   // cooperative tile load: thread i handles points 2i, 2i+1
            int i = threadIdx.x;
            const float* q = tgt + ((size_t)b * ND + jbase + 2u * i) * 3u;
            float a0 = q[0], a1 = q[1], a2 = q[2];
            float c0 = q[3], c1 = q[4], c2 = q[5];
            tileF[2 * i]     = make_float4(-2.f * a0, -2.f * c0, -2.f * a1, -2.f * c1);
            tileF[2 * i + 1] = make_float4(-2.f * a2, -2.f * c2,
                                           a0 * a0 + a1 * a1 + a2 * a2,
                                           c0 * c0 + c1 * c1 + c2 * c2);
        }
        __syncthreads();

        unsigned tileBest = 0xFFFFFFFFu;
        #pragma unroll 1
        for (int eo = 0; eo < 16; ++eo) {
            const ulonglong2* te = tp + eo * 32;
            unsigned inner = 0xFFFFFFFFu;
            #pragma unroll
            for (int ei = 0; ei < 16; ++ei) {
                ulonglong2 q0 = te[2 * ei];       // (-2y0 pair, -2y1 pair)
                ulonglong2 q1 = te[2 * ei + 1];   // (-2y2 pair,  yy  pair)
                // d = xx + yy - 2*x.y  (two points per op)
                unsigned long long d2 =
                    fma2(x0p, q0.x, fma2(x1p, q0.y, fma2(x2p, q1.x, add2(q1.y, xxp))));
                unsigned lo = (unsigned)(d2 & 0xFFFFFFFFull);
                unsigned hi = (unsigned)(d2 >> 32);
                unsigned klo = (lo & mask) | (unsigned)(2 * ei);
                unsigned khi = (hi & mask) | (unsigned)(2 * ei + 1);
                inner = min(inner, klo);
                inner = min(inner, khi);
            }
            tileBest = min(tileBest, inner | (unsigned)(eo << 5));
        }
        best = min(best, tileBest | jbase);
        __syncthreads();
    }
    atomicMin(&g_keys[(dir * NB + b) * ND + p], best);
}

// ---------------- density counts ----------------
__global__ void cnt_k() {
    int i = blockIdx.x * blockDim.x + threadIdx.x;
    if (i < TOTAL) {
        unsigned k = g_keys[i];
        atomicAdd(&g_cnt[((unsigned)i & ~(unsigned)(ND - 1)) | (k & (unsigned)(ND - 1))], 1u);
    }
}

// ---------------- final loss: exact dist recompute + weighted mean ----------------
__global__ __launch_bounds__(256)
void loss_k(const float* __restrict__ xg, const float* __restrict__ yg,
            float* __restrict__ out) {
    __shared__ float red[256];
    int i = blockIdx.x * blockDim.x + threadIdx.x;   // < 65536 exactly

    unsigned dirb = (unsigned)i >> 13;               // dir*4 + b
    unsigned p    = (unsigned)i & (ND - 1);
    unsigned dir  = dirb >> 2;
    unsigned b    = dirb & 3u;

    const float* src = dir ? yg : xg;
    const float* tg  = dir ? xg : yg;

    unsigned k   = g_keys[i];
    unsigned idx = k & (unsigned)(ND - 1);
    unsigned c   = g_cnt[((unsigned)i & ~(unsigned)(ND - 1)) | idx];

    const float* sp = src + ((size_t)b * ND + p) * 3u;
    const float* tp = tg  + ((size_t)b * ND + idx) * 3u;
    float sx0 = sp[0], sx1 = sp[1], sx2 = sp[2];
    float ty0 = tp[0], ty1 = tp[1], ty2 = tp[2];

    float xx  = sx0 * sx0 + sx1 * sx1 + sx2 * sx2;
    float yy  = ty0 * ty0 + ty1 * ty1 + ty2 * ty2;
    float dot = sx0 * ty0 + sx1 * ty1 + sx2 * ty2;
    float d   = xx - 2.0f * dot + yy;                // same expanded form as reference

    float w    = 1.0f / ((float)c + 1e-6f);          // N_LAMBDA = 1
    float term = 1.0f - expf(-d * 1000.0f) * w;      // ALPHA = 1000

    red[threadIdx.x] = term;
    __syncthreads();
    #pragma unroll
    for (int s = 128; s > 0; s >>= 1) {
        if (threadIdx.x < s) red[threadIdx.x] += red[threadIdx.x + s];
        __syncthreads();
    }
    if (threadIdx.x == 0)
        atomicAdd(out, red[0] * (1.0f / (float)TOTAL));  // mean_b((l1+l2)/2)
}

extern "C" void kernel_launch(void* const* d_in, const int* in_sizes, int n_in,
                              void* d_out, int out_size) {
    const float* x = (const float*)d_in[0];
    const float* y = (const float*)d_in[1];
    float* out = (float*)d_out;

    init_k<<<(TOTAL + 255) / 256, 256>>>(out);
    nn_k<<<2 * NB * 32 * 4, 256>>>(x, y);      // 1024 blocks
    cnt_k<<<(TOTAL + 255) / 256, 256>>>();
    loss_k<<<TOTAL / 256, 256>>>(x, y, out);
}

// round 11
// speedup vs baseline: 2.2298x; 2.2298x over previous
#include <cuda_runtime.h>
#include <cstdint>

// Shapes fixed by the problem: B=4, N=M=8192, D=3, points uniform in [0,1)^3.
#define NB 4
#define ND 8192
#define TOTAL (2 * NB * ND)      // 65536 (dir,batch,point) slots
#define G 16                     // grid resolution per axis
#define NCELL (G * G * G)        // 4096 cells per (tensor,batch)
#define NTB 8                    // 2 tensors * 4 batches

// ---------------- device scratch (no allocation allowed) ----------------
__device__ unsigned g_cellcnt[NTB * NCELL];        // histogram, then reused nowhere
__device__ unsigned g_cellfill[NTB * NCELL];       // scatter cursors
__device__ unsigned g_cellstart[NTB * (NCELL+1)];  // exclusive prefix + sentinel
__device__ float4   g_pts[NTB * ND];               // sorted (x,y,z, idx-bits)
__device__ unsigned g_keys[TOTAL];                 // nn index per (dir,b,point)
__device__ unsigned g_cnt[TOTAL];                  // density counts per direction

__device__ __forceinline__ int cell1d(float v) {
    int c = (int)(v * (float)G);
    return min(G - 1, max(0, c));
}

// ---------------- init: zero histogram, counts, output ----------------
__global__ void init_k(float* out) {
    int i = blockIdx.x * blockDim.x + threadIdx.x;
    if (i < NTB * NCELL) g_cellcnt[i] = 0u;
    if (i < TOTAL)       g_cnt[i] = 0u;
    if (i == 0)          out[0] = 0.0f;
}

// ---------------- histogram: one thread per point (both tensors) ----------------
__global__ void count_k(const float* __restrict__ x, const float* __restrict__ y) {
    int i = blockIdx.x * blockDim.x + threadIdx.x;       // [0, 65536)
    unsigned t = (unsigned)i >> 15;                       // tensor: 0=x, 1=y
    unsigned b = ((unsigned)i >> 13) & 3u;
    unsigned p = (unsigned)i & (ND - 1);
    const float* sp = (t ? y : x) + ((size_t)b * ND + p) * 3u;
    int cx = cell1d(sp[0]), cy = cell1d(sp[1]), cz = cell1d(sp[2]);
    atomicAdd(&g_cellcnt[(t * 4u + b) * NCELL + (unsigned)((cz * G + cy) * G + cx)], 1u);
}

// ---------------- exclusive scan per (tensor,batch): 8 blocks ----------------
__global__ __launch_bounds__(256)
void scan_k() {
    __shared__ unsigned sh[256];
    unsigned tb   = blockIdx.x;            // 0..7
    unsigned base = tb * NCELL;
    int t = threadIdx.x;                   // 0..255, 16 cells each
    unsigned local[16];
    unsigned sum = 0;
    #pragma unroll
    for (int j = 0; j < 16; ++j) {
        local[j] = sum;                    // exclusive within thread
        sum += g_cellcnt[base + t * 16 + j];
    }
    sh[t] = sum;
    __syncthreads();
    #pragma unroll
    for (int o = 1; o < 256; o <<= 1) {
        unsigned v = (t >= o) ? sh[t - o] : 0u;
        __syncthreads();
        sh[t] += v;
        __syncthreads();
    }
    unsigned excl = (t == 0) ? 0u : sh[t - 1];
    #pragma unroll
    for (int j = 0; j < 16; ++j) {
        unsigned s = excl + local[j];
        g_cellstart[tb * (NCELL + 1) + t * 16 + j] = s;
        g_cellfill[base + t * 16 + j] = s;
    }
    if (t == 255) g_cellstart[tb * (NCELL + 1) + NCELL] = ND;
}

// ---------------- scatter: build sorted point arrays ----------------
__global__ void scatter_k(const float* __restrict__ x, const float* __restrict__ y) {
    int i = blockIdx.x * blockDim.x + threadIdx.x;
    unsigned t = (unsigned)i >> 15;
    unsigned b = ((unsigned)i >> 13) & 3u;
    unsigned p = (unsigned)i & (ND - 1);
    const float* sp = (t ? y : x) + ((size_t)b * ND + p) * 3u;
    float p0 = sp[0], p1 = sp[1], p2 = sp[2];
    int cx = cell1d(p0), cy = cell1d(p1), cz = cell1d(p2);
    unsigned tb = t * 4u + b;
    unsigned pos = atomicAdd(&g_cellfill[tb * NCELL + (unsigned)((cz * G + cy) * G + cx)], 1u);
    g_pts[tb * ND + pos] = make_float4(p0, p1, p2, __uint_as_float(p));
}

// ---------------- candidate scan for one cell ----------------
__device__ __forceinline__ void scan_cell(const float4* __restrict__ pts,
                                          const unsigned* __restrict__ cs,
                                          int cell, float qx, float qy, float qz,
                                          float& best, unsigned& bidx) {
    unsigned s = cs[cell], e = cs[cell + 1];
    for (unsigned k = s; k < e; ++k) {
        float4 c = pts[k];
        float dx = qx - c.x, dy = qy - c.y, dz = qz - c.z;
        float d2 = dx * dx + dy * dy + dz * dz;
        unsigned ti = __float_as_uint(c.w);
        if (d2 < best || (d2 == best && ti < bidx)) { best = d2; bidx = ti; }
    }
}

// ---------------- grid NN (exact) + fused density counts ----------------
// One thread per query; queries iterate in SORTED order (warp locality),
// result written back to the query's ORIGINAL slot.
__global__ __launch_bounds__(256)
void nn_grid_k() {
    int i = blockIdx.x * blockDim.x + threadIdx.x;        // [0, 65536)
    unsigned dirb = (unsigned)i >> 13;                     // dir*4 + b
    unsigned dir  = dirb >> 2;
    unsigned b    = dirb & 3u;
    unsigned ts   = dir;                                   // src tensor (dir0: x)
    unsigned tt   = dir ^ 1u;                              // target tensor

    const float4*   qArr = g_pts + (size_t)(ts * 4u + b) * ND;
    const float4*   tArr = g_pts + (size_t)(tt * 4u + b) * ND;
    const unsigned* cs   = g_cellstart + (size_t)(tt * 4u + b) * (NCELL + 1);

    float4 q = qArr[(unsigned)i & (ND - 1)];
    float qx = q.x, qy = q.y, qz = q.z;
    unsigned orig = __float_as_uint(q.w);
    int cx = cell1d(qx), cy = cell1d(qy), cz = cell1d(qz);

    float    best = 3.0e38f;
    unsigned bidx = 0xFFFFFFFFu;

    // ring 0..1: full 3x3x3 neighborhood
    int zlo = max(cz - 1, 0), zhi = min(cz + 1, G - 1);
    int ylo = max(cy - 1, 0), yhi = min(cy + 1, G - 1);
    int xlo = max(cx - 1, 0), xhi = min(cx + 1, G - 1);
    for (int z = zlo; z <= zhi; ++z)
        for (int y = ylo; y <= yhi; ++y)
            for (int x = xlo; x <= xhi; ++x)
                scan_cell(tArr, cs, (z * G + y) * G + x, qx, qy, qz, best, bidx);

    // expand shells until guarantee: unscanned cells are >= r*h away
    const float h = 1.0f / (float)G;
    int r = 1;
    while (best > (float)(r * r) * h * h && r < G) {
        ++r;
        for (int dz = -r; dz <= r; ++dz) {
            int z = cz + dz;
            if ((unsigned)z >= (unsigned)G) continue;
            for (int dy = -r; dy <= r; ++dy) {
                int y = cy + dy;
                if ((unsigned)y >= (unsigned)G) continue;
                bool face = (dz == -r || dz == r || dy == -r || dy == r);
                int step = face ? 1 : 2 * r;
                for (int dx = -r; dx <= r; dx += step) {
                    int x = cx + dx;
                    if ((unsigned)x >= (unsigned)G) continue;
                    scan_cell(tArr, cs, (z * G + y) * G + x, qx, qy, qz, best, bidx);
                }
            }
        }
    }

    g_keys[dirb * ND + orig] = bidx;
    atomicAdd(&g_cnt[dirb * ND + bidx], 1u);
}

// ---------------- final loss: exact expanded-form dist + weighted mean ----------------
__global__ __launch_bounds__(256)
void loss_k(const float* __restrict__ xg, const float* __restrict__ yg,
            float* __restrict__ out) {
    __shared__ float red[256];
    int i = blockIdx.x * blockDim.x + threadIdx.x;       // < 65536 exactly

    unsigned dirb = (unsigned)i >> 13;                    // dir*4 + b
    unsigned p    = (unsigned)i & (ND - 1);
    unsigned dir  = dirb >> 2;
    unsigned b    = dirb & 3u;

    const float* src = dir ? yg : xg;
    const float* tg  = dir ? xg : yg;

    unsigned idx = g_keys[i] & (unsigned)(ND - 1);
    unsigned c   = g_cnt[((unsigned)i & ~(unsigned)(ND - 1)) | idx];

    const float* sp = src + ((size_t)b * ND + p) * 3u;
    const float* tp = tg  + ((size_t)b * ND + idx) * 3u;
    float sx0 = sp[0], sx1 = sp[1], sx2 = sp[2];
    float ty0 = tp[0], ty1 = tp[1], ty2 = tp[2];

    float xx  = sx0 * sx0 + sx1 * sx1 + sx2 * sx2;
    float yy  = ty0 * ty0 + ty1 * ty1 + ty2 * ty2;
    float dot = sx0 * ty0 + sx1 * ty1 + sx2 * ty2;
    float d   = xx - 2.0f * dot + yy;                     // reference's expanded form

    float w    = 1.0f / ((float)c + 1e-6f);               // N_LAMBDA = 1
    float term = 1.0f - expf(-d * 1000.0f) * w;           // ALPHA = 1000

    red[threadIdx.x] = term;
    __syncthreads();
    #pragma unroll
    for (int s = 128; s > 0; s >>= 1) {
        if (threadIdx.x < s) red[threadIdx.x] += red[threadIdx.x + s];
        __syncthreads();
    }
    if (threadIdx.x == 0)
        atomicAdd(out, red[0] * (1.0f / (float)TOTAL));   // mean_b((l1+l2)/2)
}

extern "C" void kernel_launch(void* const* d_in, const int* in_sizes, int n_in,
                              void* d_out, int out_size) {
    const float* x = (const float*)d_in[0];
    const float* y = (const float*)d_in[1];
    float* out = (float*)d_out;

    init_k   <<<(TOTAL + 255) / 256, 256>>>(out);
    count_k  <<<TOTAL / 256, 256>>>(x, y);
    scan_k   <<<NTB, 256>>>();
    scatter_k<<<TOTAL / 256, 256>>>(x, y);
    nn_grid_k<<<TOTAL / 256, 256>>>();
    loss_k   <<<TOTAL / 256, 256>>>(x, y, out);
}

// round 12
// speedup vs baseline: 2.6986x; 1.2102x over previous
#include <cuda_runtime.h>
#include <cstdint>

// Shapes fixed by the problem: B=4, N=M=8192, D=3, points uniform in [0,1)^3.
#define NB 4
#define ND 8192
#define TOTAL (2 * NB * ND)      // 65536 (dir,batch,point) slots
#define G 16                     // grid resolution per axis
#define NCELL (G * G * G)        // 4096 cells per (tensor,batch)
#define NTB 8                    // 2 tensors * 4 batches

// ---------------- device scratch (no allocation allowed) ----------------
__device__ unsigned g_cellstart[NTB * (NCELL + 1)]; // exclusive prefix + sentinel
__device__ float4   g_pts[NTB * ND];                // sorted (x,y,z, idx-bits)
__device__ unsigned g_keys[TOTAL];                  // nn index per (dir,b,point)
__device__ float    g_bd[TOTAL];                    // nn squared distance
__device__ unsigned g_cnt[TOTAL];                   // density counts per direction

__device__ __forceinline__ int cell1d(float v) {
    int c = (int)(v * (float)G);
    return min(G - 1, max(0, c));
}

// ============================================================================
// build_k: fused histogram + scan + scatter (+ zero g_cnt, out).
// 8 blocks (one per tensor,batch) x 1024 threads; 8 points per thread.
// ============================================================================
__global__ __launch_bounds__(1024)
void build_k(const float* __restrict__ x, const float* __restrict__ y,
             float* __restrict__ out) {
    __shared__ unsigned hist[NCELL];     // histogram -> cursors
    __shared__ unsigned warpsum[32];

    const unsigned tb = blockIdx.x;          // 0..7
    const unsigned t  = tb >> 2;             // tensor: 0=x, 1=y
    const unsigned b  = tb & 3u;
    const int tid = threadIdx.x;

    const float* src = (t ? y : x) + (size_t)b * ND * 3u;

    // zero histogram (4 cells/thread) + g_cnt slice (8/thread) + out
    #pragma unroll
    for (int j = 0; j < 4; ++j) hist[tid * 4 + j] = 0u;
    #pragma unroll
    for (int j = 0; j < 8; ++j) g_cnt[tb * 8192u + (unsigned)tid + j * 1024u] = 0u;
    if (tb == 0 && tid == 0) out[0] = 0.0f;
    __syncthreads();

    // ---- pass 1: histogram (keep cells in regs for scatter pass) ----
    int   mycell[8];
    float c0[8], c1[8], c2[8];
    #pragma unroll
    for (int k = 0; k < 8; ++k) {
        unsigned p = (unsigned)tid + (unsigned)k * 1024u;
        const float* sp = src + (size_t)p * 3u;
        float p0 = sp[0], p1 = sp[1], p2 = sp[2];
        c0[k] = p0; c1[k] = p1; c2[k] = p2;
        int cx = cell1d(p0), cy = cell1d(p1), cz = cell1d(p2);
        mycell[k] = (cz * G + cy) * G + cx;
        atomicAdd(&hist[mycell[k]], 1u);
    }
    __syncthreads();

    // ---- pass 2: exclusive scan of 4096 (4 per thread + 1024-scan) ----
    unsigned v0 = hist[tid * 4 + 0], v1 = hist[tid * 4 + 1];
    unsigned v2 = hist[tid * 4 + 2], v3 = hist[tid * 4 + 3];
    unsigned s = v0 + v1 + v2 + v3;

    unsigned lane = (unsigned)tid & 31u, wid = (unsigned)tid >> 5;
    unsigned inc = s;
    #pragma unroll
    for (int o = 1; o < 32; o <<= 1) {
        unsigned u = __shfl_up_sync(0xFFFFFFFFu, inc, o);
        if (lane >= (unsigned)o) inc += u;
    }
    if (lane == 31u) warpsum[wid] = inc;
    __syncthreads();
    if (wid == 0) {
        unsigned w = warpsum[lane];
        unsigned wi = w;
        #pragma unroll
        for (int o = 1; o < 32; o <<= 1) {
            unsigned u = __shfl_up_sync(0xFFFFFFFFu, wi, o);
            if (lane >= (unsigned)o) wi += u;
        }
        warpsum[lane] = wi - w;              // exclusive warp offset
    }
    __syncthreads();

    unsigned off = warpsum[wid] + (inc - s); // thread-exclusive base
    unsigned e0 = off, e1 = off + v0, e2 = e1 + v1, e3 = e2 + v2;

    unsigned* csOut = g_cellstart + (size_t)tb * (NCELL + 1);
    csOut[tid * 4 + 0] = e0;  csOut[tid * 4 + 1] = e1;
    csOut[tid * 4 + 2] = e2;  csOut[tid * 4 + 3] = e3;
    if (tid == 1023) csOut[NCELL] = ND;

    // reuse hist as scatter cursors
    hist[tid * 4 + 0] = e0;  hist[tid * 4 + 1] = e1;
    hist[tid * 4 + 2] = e2;  hist[tid * 4 + 3] = e3;
    __syncthreads();

    // ---- pass 3: scatter sorted points ----
    float4* pOut = g_pts + (size_t)tb * ND;
    #pragma unroll
    for (int k = 0; k < 8; ++k) {
        unsigned p = (unsigned)tid + (unsigned)k * 1024u;
        unsigned pos = atomicAdd(&hist[mycell[k]], 1u);
        pOut[pos] = make_float4(c0[k], c1[k], c2[k], __uint_as_float(p));
    }
}

// ---------------- candidate scan over a contiguous point range ----------------
__device__ __forceinline__ void scan_run(const float4* __restrict__ pts,
                                         unsigned s, unsigned e,
                                         float qx, float qy, float qz,
                                         float& best, unsigned& bidx) {
    for (unsigned k = s; k < e; ++k) {
        float4 c = pts[k];
        float dx = qx - c.x, dy = qy - c.y, dz = qz - c.z;
        float d2 = fmaf(dx, dx, fmaf(dy, dy, dz * dz));
        unsigned ti = __float_as_uint(c.w);
        if (d2 < best || (d2 == best && ti < bidx)) { best = d2; bidx = ti; }
    }
}

__device__ __forceinline__ void scan_cell(const float4* __restrict__ pts,
                                          const unsigned* __restrict__ cs,
                                          int cell, float qx, float qy, float qz,
                                          float& best, unsigned& bidx) {
    scan_run(pts, cs[cell], cs[cell + 1], qx, qy, qz, best, bidx);
}

// axis distance from q to cell index c's slab [c*h,(c+1)*h]
__device__ __forceinline__ float axdist(float q, int c, float h) {
    float lo = (float)c * h, hi = lo + h;
    return fmaxf(0.0f, fmaxf(lo - q, q - hi));
}

// ============================================================================
// nn_k: exact grid NN (row-run merged, row-pruned) + fused density counts.
// Queries iterate in SORTED order (warp locality); results to ORIGINAL slots.
// ============================================================================
__global__ __launch_bounds__(256)
void nn_k() {
    int i = blockIdx.x * blockDim.x + threadIdx.x;        // [0, 65536)
    unsigned dirb = (unsigned)i >> 13;                     // dir*4 + b
    unsigned dir  = dirb >> 2;
    unsigned b    = dirb & 3u;
    unsigned ts   = dir;                                   // src tensor
    unsigned tt   = dir ^ 1u;                              // target tensor

    const float4*   qArr = g_pts + (size_t)(ts * 4u + b) * ND;
    const float4*   tArr = g_pts + (size_t)(tt * 4u + b) * ND;
    const unsigned* cs   = g_cellstart + (size_t)(tt * 4u + b) * (NCELL + 1);

    float4 q = qArr[(unsigned)i & (ND - 1)];
    float qx = q.x, qy = q.y, qz = q.z;
    unsigned orig = __float_as_uint(q.w);
    int cx = cell1d(qx), cy = cell1d(qy), cz = cell1d(qz);

    const float h = 1.0f / (float)G;
    float    best = 3.0e38f;
    unsigned bidx = 0xFFFFFFFFu;

    int zlo = max(cz - 1, 0), zhi = min(cz + 1, G - 1);
    int ylo = max(cy - 1, 0), yhi = min(cy + 1, G - 1);
    int xlo = max(cx - 1, 0), xhi = min(cx + 1, G - 1);

    // center row first (establish a tight best for pruning)
    {
        int rb = (cz * G + cy) * G;
        scan_run(tArr, cs[rb + xlo], cs[rb + xhi + 1], qx, qy, qz, best, bidx);
    }
    // remaining 8 rows with min-distance pruning (strict: ties never pruned)
    for (int z = zlo; z <= zhi; ++z) {
        float dz = axdist(qz, z, h);
        float dz2 = dz * dz;
        for (int y = ylo; y <= yhi; ++y) {
            if (z == cz && y == cy) continue;
            float dy = axdist(qy, y, h);
            float bound = fmaf(dy, dy, dz2);
            if (bound > best) continue;
            int rb = (z * G + y) * G;
            scan_run(tArr, cs[rb + xlo], cs[rb + xhi + 1], qx, qy, qz, best, bidx);
        }
    }

    // expand shells until guarantee: unscanned cells are >= r*h away
    int r = 1;
    while (best > (float)(r * r) * h * h && r < G) {
        ++r;
        for (int dz = -r; dz <= r; ++dz) {
            int z = cz + dz;
            if ((unsigned)z >= (unsigned)G) continue;
            for (int dy = -r; dy <= r; ++dy) {
                int y = cy + dy;
                if ((unsigned)y >= (unsigned)G) continue;
                bool face = (dz == -r || dz == r || dy == -r || dy == r);
                int step = face ? 1 : 2 * r;
                for (int dx = -r; dx <= r; dx += step) {
                    int xcell = cx + dx;
                    if ((unsigned)xcell >= (unsigned)G) continue;
                    scan_cell(tArr, cs, (z * G + y) * G + xcell, qx, qy, qz, best, bidx);
                }
            }
        }
    }

    unsigned slot = dirb * ND + orig;
    g_keys[slot] = bidx;
    g_bd[slot]   = best;
    atomicAdd(&g_cnt[dirb * ND + bidx], 1u);
}

// ============================================================================
// loss_k: term from stored d^2 + counts, block reduce, single atomic per block
// ============================================================================
__global__ __launch_bounds__(256)
void loss_k(float* __restrict__ out) {
    __shared__ float red[256];
    int i = blockIdx.x * blockDim.x + threadIdx.x;        // < 65536 exactly

    unsigned idx = g_keys[i] & (unsigned)(ND - 1);
    unsigned c   = g_cnt[((unsigned)i & ~(unsigned)(ND - 1)) | idx];
    float d      = g_bd[i];

    float w    = 1.0f / ((float)c + 1e-6f);               // N_LAMBDA = 1
    float term = 1.0f - expf(-d * 1000.0f) * w;           // ALPHA = 1000

    red[threadIdx.x] = term;
    __syncthreads();
    #pragma unroll
    for (int s = 128; s > 32; s >>= 1) {
        if (threadIdx.x < s) red[threadIdx.x] += red[threadIdx.x + s];
        __syncthreads();
    }
    if (threadIdx.x < 32) {
        float v = red[threadIdx.x] + red[threadIdx.x + 32];
        #pragma unroll
        for (int o = 16; o > 0; o >>= 1)
            v += __shfl_down_sync(0xFFFFFFFFu, v, o);
        if (threadIdx.x == 0)
            atomicAdd(out, v * (1.0f / (float)TOTAL));    // mean_b((l1+l2)/2)
    }
}

extern "C" void kernel_launch(void* const* d_in, const int* in_sizes, int n_in,
                              void* d_out, int out_size) {
    const float* x = (const float*)d_in[0];
    const float* y = (const float*)d_in[1];
    float* out = (float*)d_out;

    build_k<<<NTB, 1024>>>(x, y, out);
    nn_k   <<<TOTAL / 256, 256>>>();
    loss_k <<<TOTAL / 256, 256>>>(out);
}

// round 14
// speedup vs baseline: 2.7246x; 1.0096x over previous
#include <cuda_runtime.h>
#include <cstdint>

// Shapes fixed by the problem: B=4, N=M=8192, D=3, points uniform in [0,1)^3.
#define NB 4
#define ND 8192
#define TOTAL (2 * NB * ND)      // 65536 (dir,batch,point) slots
#define G 16                     // grid resolution per axis
#define NCELL (G * G * G)        // 4096 cells per (tensor,batch)
#define NTB 8                    // 2 tensors * 4 batches

// ---------------- device scratch (no allocation allowed) ----------------
__device__ unsigned short g_cs[NTB * (NCELL + 1)];  // exclusive prefix + sentinel
__device__ float4   g_pts[NTB * ND];                // sorted (x,y,z, idx-bits)
__device__ unsigned g_keys[TOTAL];                  // nn index per (dir,b,point)
__device__ float    g_e[TOTAL];                     // exp(-1000 * nn_d2)
__device__ unsigned g_cnt[TOTAL];                   // density counts per direction

__device__ __forceinline__ int cell1d(float v) {
    int c = (int)(v * (float)G);
    return min(G - 1, max(0, c));
}

// ============================================================================
// build_k: fused histogram + scan + scatter (+ zero g_cnt FULLY, out).
// 8 blocks (one per tensor,batch) x 1024 threads; 8 consecutive points/thread
// loaded as 6 float4s (96B contiguous per thread).
// ============================================================================
__global__ __launch_bounds__(1024)
void build_k(const float* __restrict__ x, const float* __restrict__ y,
             float* __restrict__ out) {
    __shared__ unsigned hist[NCELL];     // histogram -> cursors
    __shared__ unsigned warpsum[32];

    const unsigned tb = blockIdx.x;          // 0..7
    const unsigned t  = tb >> 2;             // tensor: 0=x, 1=y
    const unsigned b  = tb & 3u;
    const int tid = threadIdx.x;

    const float4* src4 = reinterpret_cast<const float4*>(
        (t ? y : x) + (size_t)b * ND * 3u);

    // zero histogram (4 cells/thread, vector) + FULL g_cnt slice (8192) + out.
    // NOTE: must cover all 8192 entries every call — graph replays reuse state.
    reinterpret_cast<uint4*>(hist)[tid] = make_uint4(0u, 0u, 0u, 0u);
    {
        uint4* cz = reinterpret_cast<uint4*>(g_cnt + tb * 8192u);
        cz[tid]        = make_uint4(0u, 0u, 0u, 0u);
        cz[tid + 1024] = make_uint4(0u, 0u, 0u, 0u);
    }
    if (tb == 0 && tid == 0) out[0] = 0.0f;
    __syncthreads();

    // ---- pass 1: vector load 8 points, histogram ----
    float4 f[6];
    #pragma unroll
    for (int j = 0; j < 6; ++j) f[j] = src4[tid * 6 + j];
    const float* fl = reinterpret_cast<const float*>(f);

    int mycell[8];
    #pragma unroll
    for (int m = 0; m < 8; ++m) {
        int cx = cell1d(fl[3 * m + 0]);
        int cy = cell1d(fl[3 * m + 1]);
        int cz = cell1d(fl[3 * m + 2]);
        mycell[m] = (cz * G + cy) * G + cx;
        atomicAdd(&hist[mycell[m]], 1u);
    }
    __syncthreads();

    // ---- pass 2: exclusive scan of 4096 (4 per thread + 1024-scan) ----
    uint4 hv = reinterpret_cast<const uint4*>(hist)[tid];
    unsigned s = hv.x + hv.y + hv.z + hv.w;

    unsigned lane = (unsigned)tid & 31u, wid = (unsigned)tid >> 5;
    unsigned inc = s;
    #pragma unroll
    for (int o = 1; o < 32; o <<= 1) {
        unsigned u = __shfl_up_sync(0xFFFFFFFFu, inc, o);
        if (lane >= (unsigned)o) inc += u;
    }
    if (lane == 31u) warpsum[wid] = inc;
    __syncthreads();
    if (wid == 0) {
        unsigned w = warpsum[lane];
        unsigned wi = w;
        #pragma unroll
        for (int o = 1; o < 32; o <<= 1) {
            unsigned u = __shfl_up_sync(0xFFFFFFFFu, wi, o);
            if (lane >= (unsigned)o) wi += u;
        }
        warpsum[lane] = wi - w;              // exclusive warp offset
    }
    __syncthreads();

    unsigned off = warpsum[wid] + (inc - s); // thread-exclusive base
    unsigned e0 = off, e1 = off + hv.x, e2 = e1 + hv.y, e3 = e2 + hv.z;

    unsigned short* csOut = g_cs + (size_t)tb * (NCELL + 1);
    csOut[tid * 4 + 0] = (unsigned short)e0;
    csOut[tid * 4 + 1] = (unsigned short)e1;
    csOut[tid * 4 + 2] = (unsigned short)e2;
    csOut[tid * 4 + 3] = (unsigned short)e3;
    if (tid == 1023) csOut[NCELL] = (unsigned short)ND;

    __syncthreads();                         // hist reads done before overwrite
    // reuse hist as scatter cursors
    reinterpret_cast<uint4*>(hist)[tid] = make_uint4(e0, e1, e2, e3);
    __syncthreads();

    // ---- pass 3: scatter sorted points ----
    float4* pOut = g_pts + (size_t)tb * ND;
    #pragma unroll
    for (int m = 0; m < 8; ++m) {
        unsigned p = (unsigned)tid * 8u + (unsigned)m;
        unsigned pos = atomicAdd(&hist[mycell[m]], 1u);
        pOut[pos] = make_float4(fl[3 * m + 0], fl[3 * m + 1], fl[3 * m + 2],
                                __uint_as_float(p));
    }
}

// ---------------- candidate scan with 1-deep prefetch ----------------
__device__ __forceinline__ void scan_run(const float4* __restrict__ pts,
                                         unsigned s, unsigned e,
                                         float qx, float qy, float qz,
                                         float& best, unsigned& bidx) {
    if (s >= e) return;
    float4 c = pts[s];
    for (unsigned k = s + 1; k < e; ++k) {
        float4 nxt = pts[k];
        float dx = qx - c.x, dy = qy - c.y, dz = qz - c.z;
        float d2 = fmaf(dx, dx, fmaf(dy, dy, dz * dz));
        unsigned ti = __float_as_uint(c.w);
        if (d2 < best || (d2 == best && ti < bidx)) { best = d2; bidx = ti; }
        c = nxt;
    }
    float dx = qx - c.x, dy = qy - c.y, dz = qz - c.z;
    float d2 = fmaf(dx, dx, fmaf(dy, dy, dz * dz));
    unsigned ti = __float_as_uint(c.w);
    if (d2 < best || (d2 == best && ti < bidx)) { best = d2; bidx = ti; }
}

// axis distance from q to cell index c's slab [c*h,(c+1)*h]
__device__ __forceinline__ float axdist(float q, int c, float h) {
    float lo = (float)c * h, hi = lo + h;
    return fmaxf(0.0f, fmaxf(lo - q, q - hi));
}

// ============================================================================
// nn_k: exact grid NN. All 9 row-run bounds loaded up front (u16, L1-resident)
// for MLP; center row scanned first; other rows pruned strictly by min row
// distance; rare shell-expansion fallback guarantees exactness. Fused counts.
// ============================================================================
__global__ __launch_bounds__(256)
void nn_k() {
    int i = blockIdx.x * blockDim.x + threadIdx.x;        // [0, 65536)
    unsigned dirb = (unsigned)i >> 13;                     // dir*4 + b
    unsigned dir  = dirb >> 2;
    unsigned b    = dirb & 3u;
    unsigned ts   = dir;                                   // src tensor
    unsigned tt   = dir ^ 1u;                              // target tensor

    const float4*         qArr = g_pts + (size_t)(ts * 4u + b) * ND;
    const float4*         tArr = g_pts + (size_t)(tt * 4u + b) * ND;
    const unsigned short* cs   = g_cs  + (size_t)(tt * 4u + b) * (NCELL + 1);

    float4 q = qArr[(unsigned)i & (ND - 1)];
    float qx = q.x, qy = q.y, qz = q.z;
    unsigned orig = __float_as_uint(q.w);
    int cx = cell1d(qx), cy = cell1d(qy), cz = cell1d(qz);

    const float h = 1.0f / (float)G;
    float    best = 3.0e38f;
    unsigned bidx = 0xFFFFFFFFu;

    int xlo = max(cx - 1, 0), xhi = min(cx + 1, G - 1);

    // front-load all 9 row-run bounds (independent loads -> MLP)
    unsigned rs[9], re[9];
    float    rbound[9];
    #pragma unroll
    for (int zi = 0; zi < 3; ++zi) {
        int z = cz + zi - 1;
        bool zok = (unsigned)z < (unsigned)G;
        float dz = zok ? axdist(qz, z, h) : 0.0f;
        #pragma unroll
        for (int yi = 0; yi < 3; ++yi) {
            int y = cy + yi - 1;
            bool ok = zok && ((unsigned)y < (unsigned)G);
            int k = zi * 3 + yi;
            int rb = ((z & (G - 1)) * G + (y & (G - 1))) * G;  // safe index
            unsigned sS = cs[rb + xlo], sE = cs[rb + xhi + 1];
            rs[k] = ok ? sS : 0u;
            re[k] = ok ? sE : 0u;
            float dy = axdist(qy, y & (G - 1), h);
            rbound[k] = fmaf(dy, dy, dz * dz);
        }
    }

    // center row first (tight best for pruning), then the rest
    scan_run(tArr, rs[4], re[4], qx, qy, qz, best, bidx);
    #pragma unroll
    for (int k = 0; k < 9; ++k) {
        if (k == 4) continue;
        if (rbound[k] <= best)
            scan_run(tArr, rs[k], re[k], qx, qy, qz, best, bidx);
    }

    // rare fallback: expand shells until unscanned cells are >= r*h away
    int r = 1;
    while (best > (float)(r * r) * h * h && r < G) {
        ++r;
        for (int dz = -r; dz <= r; ++dz) {
            int z = cz + dz;
            if ((unsigned)z >= (unsigned)G) continue;
            for (int dy = -r; dy <= r; ++dy) {
                int y = cy + dy;
                if ((unsigned)y >= (unsigned)G) continue;
                bool face = (dz == -r || dz == r || dy == -r || dy == r);
                int step = face ? 1 : 2 * r;
                for (int dx = -r; dx <= r; dx += step) {
                    int xc = cx + dx;
                    if ((unsigned)xc >= (unsigned)G) continue;
                    int cell = (z * G + y) * G + xc;
                    scan_run(tArr, cs[cell], cs[cell + 1], qx, qy, qz, best, bidx);
                }
            }
        }
    }

    unsigned slot = dirb * ND + orig;
    g_keys[slot] = bidx;
    g_e[slot]    = __expf(-1000.0f * best);               // ALPHA = 1000
    atomicAdd(&g_cnt[dirb * ND + bidx], 1u);
}

// ============================================================================
// loss_k: 4 items/thread (vector loads), block reduce, one atomic per block
// ============================================================================
__global__ __launch_bounds__(256)
void loss_k(float* __restrict__ out) {
    __shared__ float red[256];
    int tid = threadIdx.x;
    int i4 = blockIdx.x * 256 + tid;                      // [0, 16384)

    uint4  kk = reinterpret_cast<const uint4*>(g_keys)[i4];
    float4 ee = reinterpret_cast<const float4*>(g_e)[i4];
    unsigned seg = ((unsigned)i4 * 4u) & ~(unsigned)(ND - 1);

    unsigned c0 = g_cnt[seg | (kk.x & (ND - 1))];
    unsigned c1 = g_cnt[seg | (kk.y & (ND - 1))];
    unsigned c2 = g_cnt[seg | (kk.z & (ND - 1))];
    unsigned c3 = g_cnt[seg | (kk.w & (ND - 1))];

    float v = (1.0f - ee.x / ((float)c0 + 1e-6f))
            + (1.0f - ee.y / ((float)c1 + 1e-6f))
            + (1.0f - ee.z / ((float)c2 + 1e-6f))
            + (1.0f - ee.w / ((float)c3 + 1e-6f));

    red[tid] = v;
    __syncthreads();
    #pragma unroll
    for (int s = 128; s > 32; s >>= 1) {
        if (tid < s) red[tid] += red[tid + s];
        __syncthreads();
    }
    if (tid < 32) {
        float w = red[tid] + red[tid + 32];
        #pragma unroll
        for (int o = 16; o > 0; o >>= 1)
            w += __shfl_down_sync(0xFFFFFFFFu, w, o);
        if (tid == 0)
            atomicAdd(out, w * (1.0f / (float)TOTAL));    // mean_b((l1+l2)/2)
    }
}

extern "C" void kernel_launch(void* const* d_in, const int* in_sizes, int n_in,
                              void* d_out, int out_size) {
    const float* x = (const float*)d_in[0];
    const float* y = (const float*)d_in[1];
    float* out = (float*)d_out;

    build_k<<<NTB, 1024>>>(x, y, out);
    nn_k   <<<TOTAL / 256, 256>>>();
    loss_k <<<TOTAL / 1024, 256>>>(out);
}